// round 2
// baseline (speedup 1.0000x reference)
#include <cuda_runtime.h>
#include <cuda_fp16.h>
#include <stdint.h>

#define SQ 2048
#define DD 256
#define CCH 64
#define TH 48
#define NGRP 24
#define OPITCH 260

// ---------------- static device scratch (no cudaMalloc allowed) ----------------
__device__ __align__(16) __half g_nodes[SQ * DD];
__device__ __align__(16) __half g_Wn[2048 * 256];
__device__ __align__(16) __half g_Wv[12288 * 256];
__device__ __align__(16) __half g_K[TH * SQ * CCH];   // [h][s][c]
__device__ __align__(16) __half g_Qm[TH * SQ * CCH];  // [h][s][c]
__device__ __align__(16) __half g_V[TH * SQ * DD];    // [h][s][d]
__device__ float g_part[NGRP][SQ * DD];

// ---------------- helpers ----------------
static __device__ __forceinline__ uint32_t sm_u32(const void* p) {
    return (uint32_t)__cvta_generic_to_shared(p);
}
static __device__ __forceinline__ void ldsm4(uint32_t* r, uint32_t a) {
    asm volatile("ldmatrix.sync.aligned.m8n8.x4.shared.b16 {%0,%1,%2,%3},[%4];"
                 : "=r"(r[0]), "=r"(r[1]), "=r"(r[2]), "=r"(r[3]) : "r"(a));
}
static __device__ __forceinline__ void ldsm4t(uint32_t* r, uint32_t a) {
    asm volatile("ldmatrix.sync.aligned.m8n8.x4.trans.shared.b16 {%0,%1,%2,%3},[%4];"
                 : "=r"(r[0]), "=r"(r[1]), "=r"(r[2]), "=r"(r[3]) : "r"(a));
}
static __device__ __forceinline__ void mma16816(float* c, const uint32_t* a, const uint32_t* b) {
    asm volatile("mma.sync.aligned.m16n8k16.row.col.f32.f16.f16.f32 "
                 "{%0,%1,%2,%3},{%4,%5,%6,%7},{%8,%9},{%0,%1,%2,%3};"
                 : "+f"(c[0]), "+f"(c[1]), "+f"(c[2]), "+f"(c[3])
                 : "r"(a[0]), "r"(a[1]), "r"(a[2]), "r"(a[3]), "r"(b[0]), "r"(b[1]));
}
static __device__ __forceinline__ uint32_t packh2(float x, float y) {
    __half2 h = __floats2half2_rn(x, y);
    return *reinterpret_cast<uint32_t*>(&h);
}
// polynomial exp: avoids MUFU (rt=8/SMSP would cost ~1.5ms for 201M exps)
static __device__ __forceinline__ float fexp(float x) {
    x = fminf(fmaxf(x, -20.f), 20.f);
    float t = x * 1.4426950408889634f;
    float z = t + 12582912.0f;           // round-to-nearest-int magic
    float n = z - 12582912.0f;
    float f = t - n;
    int e = ((__float_as_int(z) - 0x4B400000) + 127) << 23;
    float p = 1.3333558e-3f;
    p = fmaf(p, f, 9.6181291e-3f);
    p = fmaf(p, f, 5.55041087e-2f);
    p = fmaf(p, f, 2.402265069e-1f);
    p = fmaf(p, f, 6.931471806e-1f);
    p = fmaf(p, f, 1.0f);
    return p * __int_as_float(e);
}

// ---------------- kernel 1: fp32 -> fp16 conversion ----------------
__global__ void k_convert(const float* __restrict__ nodes,
                          const float* __restrict__ Wn,
                          const float* __restrict__ Wv) {
    const int nN = SQ * DD / 4, nWn = 2048 * 256 / 4, nWv = 12288 * 256 / 4;
    int stride = gridDim.x * blockDim.x;
    for (int idx = blockIdx.x * blockDim.x + threadIdx.x; idx < nN + nWn + nWv; idx += stride) {
        const float* src; __half* dst; int j;
        if (idx < nN)            { src = nodes; dst = g_nodes; j = idx; }
        else if (idx < nN + nWn) { src = Wn;    dst = g_Wn;    j = idx - nN; }
        else                     { src = Wv;    dst = g_Wv;    j = idx - nN - nWn; }
        float4 v = ((const float4*)src)[j];
        ((__half2*)dst)[2 * j]     = __floats2half2_rn(v.x, v.y);
        ((__half2*)dst)[2 * j + 1] = __floats2half2_rn(v.z, v.w);
    }
}

// ---------------- kernel 2: pos/rot projections (K=6 / K=4) ----------------
__global__ void k_posrot(const float* __restrict__ pos, const float* __restrict__ rot,
                         const float* __restrict__ Wp, const float* __restrict__ bp,
                         const float* __restrict__ Wr) {
    int idx = blockIdx.x * blockDim.x + threadIdx.x;
    if (idx >= SQ * 2048) return;
    int s = idx >> 11, r = idx & 2047;
    float ap = bp[r];
#pragma unroll
    for (int i = 0; i < 6; i++) ap = fmaf(pos[s * 6 + i], Wp[r * 6 + i], ap);
    float ar = 0.f;
#pragma unroll
    for (int i = 0; i < 4; i++) ar = fmaf(rot[s * 4 + i], Wr[r * 4 + i], ar);
    int h = r >> 7, cc = r & 127;
    if (cc < 64) {
        g_K[(16 + h) * SQ * CCH + s * CCH + cc] = __float2half_rn(ap);
        g_K[(32 + h) * SQ * CCH + s * CCH + cc] = __float2half_rn(ar);
    } else {
        g_Qm[(16 + h) * SQ * CCH + s * CCH + cc - 64] = __float2half_rn(ap);
        g_Qm[(32 + h) * SQ * CCH + s * CCH + cc - 64] = __float2half_rn(ar);
    }
}

// ---------------- kernel 3: fp16 mma GEMM: nodes @ W^T + bias, scatter ----------------
// MODE 0: W=Wn (2048 out) -> g_K / g_Qm node heads.  MODE 1: W=Wv (12288 out) -> g_V.
template <int MODE>
__global__ __launch_bounds__(256) void k_gemm(const float* __restrict__ bias) {
    __shared__ __half As[128 * 64];
    __shared__ __half Bs[128 * 64];
    const __half* Wg = (MODE == 0) ? g_Wn : g_Wv;
    int mb = blockIdx.x * 128, nb = blockIdx.y * 128;
    int t = threadIdx.x, lane = t & 31, w = t >> 5;
    int wm = w & 3, wn = w >> 2;   // 4x2 warp grid, warp tile 32m x 64n
    float c[2][8][4];
#pragma unroll
    for (int a = 0; a < 2; a++)
#pragma unroll
        for (int b = 0; b < 8; b++)
#pragma unroll
            for (int e2 = 0; e2 < 4; e2++) c[a][b][e2] = 0.f;

    for (int kc = 0; kc < 4; kc++) {
#pragma unroll
        for (int i = 0; i < 4; i++) {
            int l = t + i * 256;
            int row = l >> 3, ch = l & 7;
            int sw = (ch ^ (row & 7)) * 8;
            *(int4*)&As[row * 64 + sw] = *(const int4*)&g_nodes[(mb + row) * 256 + kc * 64 + ch * 8];
            *(int4*)&Bs[row * 64 + sw] = *(const int4*)&Wg[(nb + row) * 256 + kc * 64 + ch * 8];
        }
        __syncthreads();
#pragma unroll
        for (int ks = 0; ks < 4; ks++) {
            uint32_t a[2][4];
#pragma unroll
            for (int ms = 0; ms < 2; ms++) {
                int row = wm * 32 + ms * 16 + (lane & 15);
                int col = (ks * 16 + ((lane >> 4) << 3)) ^ ((row & 7) << 3);
                ldsm4(a[ms], sm_u32(&As[row * 64 + col]));
            }
#pragma unroll
            for (int p = 0; p < 4; p++) {
                uint32_t b[4];
                int row = wn * 64 + p * 16 + (lane & 7) + ((lane & 16) >> 1);
                int col = (ks * 16 + (lane & 8)) ^ ((row & 7) << 3);
                ldsm4(b, sm_u32(&Bs[row * 64 + col]));
                mma16816(c[0][2 * p],     a[0], b);
                mma16816(c[0][2 * p + 1], a[0], b + 2);
                mma16816(c[1][2 * p],     a[1], b);
                mma16816(c[1][2 * p + 1], a[1], b + 2);
            }
        }
        __syncthreads();
    }
    // epilogue: +bias, fp16, scatter to per-head layout
#pragma unroll
    for (int ms = 0; ms < 2; ms++) {
        int r0 = mb + wm * 32 + ms * 16 + (lane >> 2);
#pragma unroll
        for (int nt = 0; nt < 8; nt++) {
            int n = nb + wn * 64 + nt * 8 + 2 * (lane & 3);
            float b0 = bias[n], b1 = bias[n + 1];
            uint32_t lo = packh2(c[ms][nt][0] + b0, c[ms][nt][1] + b1);
            uint32_t hi = packh2(c[ms][nt][2] + b0, c[ms][nt][3] + b1);
            if (MODE == 0) {
                int h = n >> 7, ccv = n & 127;
                __half* dst = (ccv < 64) ? (g_K + h * SQ * CCH + ccv)
                                         : (g_Qm + h * SQ * CCH + (ccv - 64));
                *(uint32_t*)&dst[r0 * CCH]       = lo;
                *(uint32_t*)&dst[(r0 + 8) * CCH] = hi;
            } else {
                int h = n >> 8, d = n & 255;
                __half* dst = g_V + h * SQ * DD + d;
                *(uint32_t*)&dst[r0 * DD]       = lo;
                *(uint32_t*)&dst[(r0 + 8) * DD] = hi;
            }
        }
    }
}

// ---------------- kernel 4: fused attention ----------------
// grid (16 i-tiles of 128, 24 head-groups of 2). 8 warps x 16 rows x 256 cols.
// No max-subtraction (logits bounded ~ +-1.5): plain sum-exp softmax.
__global__ __launch_bounds__(256, 1) void k_attn() {
    extern __shared__ char smem_raw[];
    float*  Oa = (float*)smem_raw;                                   // 128 x OPITCH fp32
    __half* Qs = (__half*)(smem_raw + 128 * OPITCH * 4);             // 64 x 64
    __half* Vs = (__half*)(smem_raw + 128 * OPITCH * 4 + 64 * 64 * 2); // 64 x 256
    int t = threadIdx.x, lane = t & 31, w = t >> 5;
    int ib = blockIdx.x * 128;
    int grp = blockIdx.y;

    for (int i = t; i < 128 * OPITCH; i += 256) Oa[i] = 0.f;
    uint32_t qbase = sm_u32(Qs), vbase = sm_u32(Vs);

    for (int e = 0; e < 2; e++) {
        int h = grp * 2 + e;
        bool isrot = (h >= 32);
        // K a-frags directly from global (16 rows per warp, resident all head)
        uint32_t ak[4][4];
        {
            const __half* kb = g_K + h * SQ * CCH + (ib + w * 16) * CCH;
            int r = lane >> 2, c0 = 2 * (lane & 3);
#pragma unroll
            for (int ks = 0; ks < 4; ks++) {
                int cb = ks * 16 + c0;
                ak[ks][0] = *(const uint32_t*)&kb[r * CCH + cb];
                ak[ks][1] = *(const uint32_t*)&kb[(r + 8) * CCH + cb];
                ak[ks][2] = *(const uint32_t*)&kb[r * CCH + cb + 8];
                ak[ks][3] = *(const uint32_t*)&kb[(r + 8) * CCH + cb + 8];
            }
        }
        float o[32][4];
#pragma unroll
        for (int i = 0; i < 32; i++) { o[i][0] = 0.f; o[i][1] = 0.f; o[i][2] = 0.f; o[i][3] = 0.f; }
        float l0 = 0.f, l1 = 0.f;
        const __half* qg = g_Qm + h * SQ * CCH;
        const __half* vg = g_V + h * SQ * DD;

        for (int jt = 0; jt < 32; jt++) {
            __syncthreads();
#pragma unroll
            for (int i = 0; i < 2; i++) {          // Q tile 64x64
                int l = t + i * 256;
                int row = l >> 3, ch = l & 7;
                int sw = (ch ^ (row & 7)) * 8;
                *(int4*)&Qs[row * 64 + sw] = *(const int4*)&qg[(jt * 64 + row) * CCH + ch * 8];
            }
#pragma unroll
            for (int i = 0; i < 8; i++) {          // V tile 64x256
                int l = t + i * 256;
                int row = l >> 5, ch = l & 31;
                int sw = (ch ^ (row & 7)) * 8;
                *(int4*)&Vs[row * 256 + sw * 1] = *(const int4*)&vg[(jt * 64 + row) * DD + ch * 8];
            }
            __syncthreads();

            float sc[8][4];
#pragma unroll
            for (int i = 0; i < 8; i++) { sc[i][0] = 0.f; sc[i][1] = 0.f; sc[i][2] = 0.f; sc[i][3] = 0.f; }
            // S = K_i @ Q_j^T  (16 x 64 per warp)
#pragma unroll
            for (int ks = 0; ks < 4; ks++) {
#pragma unroll
                for (int p = 0; p < 4; p++) {
                    uint32_t qb[4];
                    int row = p * 16 + (lane & 7) + ((lane & 16) >> 1);
                    int col = (ks * 16 + (lane & 8)) ^ ((row & 7) << 3);
                    ldsm4(qb, qbase + (row * 64 + col) * 2);
                    mma16816(sc[2 * p],     ak[ks], qb);
                    mma16816(sc[2 * p + 1], ak[ks], qb + 2);
                }
            }
            // square (rot heads), scale 1/sqrt(16), exp, sum
#pragma unroll
            for (int i = 0; i < 8; i++) {
#pragma unroll
                for (int q2 = 0; q2 < 4; q2++) {
                    float x = sc[i][q2];
                    if (isrot) x = x * x;
                    sc[i][q2] = fexp(x * 0.25f);
                }
                l0 += sc[i][0] + sc[i][1];
                l1 += sc[i][2] + sc[i][3];
            }
            // O += P @ V  (P cfrag -> A-frag identity, V via ldmatrix.trans)
#pragma unroll
            for (int ks = 0; ks < 4; ks++) {
                uint32_t pa[4];
                pa[0] = packh2(sc[2 * ks][0],     sc[2 * ks][1]);
                pa[1] = packh2(sc[2 * ks][2],     sc[2 * ks][3]);
                pa[2] = packh2(sc[2 * ks + 1][0], sc[2 * ks + 1][1]);
                pa[3] = packh2(sc[2 * ks + 1][2], sc[2 * ks + 1][3]);
#pragma unroll
                for (int ndp = 0; ndp < 16; ndp++) {
                    uint32_t vb[4];
                    int row = ks * 16 + (lane & 15);
                    int col = (ndp * 16 + ((lane >> 4) << 3)) ^ ((row & 7) << 3);
                    ldsm4t(vb, vbase + (row * 256 + col) * 2);
                    mma16816(o[2 * ndp],     pa, vb);
                    mma16816(o[2 * ndp + 1], pa, vb + 2);
                }
            }
        }
        // softmax denominators (quad reduce) and fold into smem accumulator
        l0 += __shfl_xor_sync(0xffffffffu, l0, 1);
        l0 += __shfl_xor_sync(0xffffffffu, l0, 2);
        l1 += __shfl_xor_sync(0xffffffffu, l1, 1);
        l1 += __shfl_xor_sync(0xffffffffu, l1, 2);
        float inv0 = 1.f / l0, inv1 = 1.f / l1;
        int r0 = w * 16 + (lane >> 2);
        int cbase = 2 * (lane & 3);
#pragma unroll
        for (int nt = 0; nt < 32; nt++) {
            int col = nt * 8 + cbase;
            float* p0 = &Oa[r0 * OPITCH + col];
            p0[0] += o[nt][0] * inv0; p0[1] += o[nt][1] * inv0;
            float* p1 = &Oa[(r0 + 8) * OPITCH + col];
            p1[0] += o[nt][2] * inv1; p1[1] += o[nt][3] * inv1;
        }
    }
    __syncthreads();
    float* dst = g_part[grp] + ib * DD;
    for (int i = t; i < 128 * 64; i += 256) {   // 8192 float4
        int row = i >> 6, colf = (i & 63) * 4;
        *(float4*)&dst[row * DD + colf] = *(float4*)&Oa[row * OPITCH + colf];
    }
}

// ---------------- kernel 5: deterministic bucket reduction ----------------
__global__ void k_reduce(float* __restrict__ out) {
    int i = blockIdx.x * blockDim.x + threadIdx.x;   // float4 index
    float4 acc = make_float4(0.f, 0.f, 0.f, 0.f);
#pragma unroll
    for (int b = 0; b < NGRP; b++) {
        float4 v = *(const float4*)&g_part[b][i * 4];
        acc.x += v.x; acc.y += v.y; acc.z += v.z; acc.w += v.w;
    }
    ((float4*)out)[i] = acc;
}

// ---------------- launch ----------------
extern "C" void kernel_launch(void* const* d_in, const int* in_sizes, int n_in,
                              void* d_out, int out_size) {
    const float* nodes = (const float*)d_in[0];
    const float* pos   = (const float*)d_in[1];
    const float* rot   = (const float*)d_in[2];
    const float* Wn    = (const float*)d_in[3];
    const float* bn    = (const float*)d_in[4];
    const float* Wp    = (const float*)d_in[5];
    const float* bp    = (const float*)d_in[6];
    const float* Wr    = (const float*)d_in[7];
    const float* Wv    = (const float*)d_in[8];
    const float* bv    = (const float*)d_in[9];
    (void)in_sizes; (void)n_in; (void)out_size;

    const int attn_smem = 128 * OPITCH * 4 + 64 * 64 * 2 + 64 * 256 * 2;  // 174080 B
    cudaFuncSetAttribute(k_attn, cudaFuncAttributeMaxDynamicSharedMemorySize, attn_smem);

    k_convert<<<4096, 256>>>(nodes, Wn, Wv);
    k_posrot<<<(SQ * 2048) / 256, 256>>>(pos, rot, Wp, bp, Wr);
    k_gemm<0><<<dim3(16, 16), 256>>>(bn);
    k_gemm<1><<<dim3(16, 96), 256>>>(bv);
    k_attn<<<dim3(16, NGRP), 256, attn_smem>>>();
    k_reduce<<<512, 256>>>((float*)d_out);
}

// round 4
// speedup vs baseline: 1.0950x; 1.0950x over previous
#include <cuda_runtime.h>
#include <cuda_fp16.h>
#include <stdint.h>

#define SQ 2048
#define DD 256
#define CCH 64
#define TH 48
#define NGRP 48

// ---------------- static device scratch (no cudaMalloc allowed) ----------------
__device__ __align__(16) __half g_nodes[SQ * DD];
__device__ __align__(16) __half g_Wn[2048 * 256];
__device__ __align__(16) __half g_Wv[12288 * 256];
__device__ __align__(16) __half g_K[TH * SQ * CCH];   // [h][s][c]
__device__ __align__(16) __half g_Qm[TH * SQ * CCH];  // [h][s][c]
__device__ __align__(16) __half g_V[TH * SQ * DD];    // [h][s][d]
__device__ float g_part[NGRP][SQ * DD];               // per-head partials

// ---------------- helpers ----------------
static __device__ __forceinline__ uint32_t sm_u32(const void* p) {
    return (uint32_t)__cvta_generic_to_shared(p);
}
static __device__ __forceinline__ void ldsm4(uint32_t* r, uint32_t a) {
    asm volatile("ldmatrix.sync.aligned.m8n8.x4.shared.b16 {%0,%1,%2,%3},[%4];"
                 : "=r"(r[0]), "=r"(r[1]), "=r"(r[2]), "=r"(r[3]) : "r"(a));
}
static __device__ __forceinline__ void ldsm4t(uint32_t* r, uint32_t a) {
    asm volatile("ldmatrix.sync.aligned.m8n8.x4.trans.shared.b16 {%0,%1,%2,%3},[%4];"
                 : "=r"(r[0]), "=r"(r[1]), "=r"(r[2]), "=r"(r[3]) : "r"(a));
}
static __device__ __forceinline__ void mma16816(float* c, const uint32_t* a, const uint32_t* b) {
    asm volatile("mma.sync.aligned.m16n8k16.row.col.f32.f16.f16.f32 "
                 "{%0,%1,%2,%3},{%4,%5,%6,%7},{%8,%9},{%0,%1,%2,%3};"
                 : "+f"(c[0]), "+f"(c[1]), "+f"(c[2]), "+f"(c[3])
                 : "r"(a[0]), "r"(a[1]), "r"(a[2]), "r"(a[3]), "r"(b[0]), "r"(b[1]));
}
static __device__ __forceinline__ uint32_t packh2(float x, float y) {
    __half2 h = __floats2half2_rn(x, y);
    return *reinterpret_cast<uint32_t*>(&h);
}
// polynomial exp on the FMA pipe (MUFU rt=8/SMSP would be a throughput wall for 201M exps)
static __device__ __forceinline__ float fexp(float x) {
    x = fminf(fmaxf(x, -20.f), 20.f);
    float t = x * 1.4426950408889634f;
    float z = t + 12582912.0f;
    float n = z - 12582912.0f;
    float f = t - n;
    int e = ((__float_as_int(z) - 0x4B400000) + 127) << 23;
    float p = 1.3333558e-3f;
    p = fmaf(p, f, 9.6181291e-3f);
    p = fmaf(p, f, 5.55041087e-2f);
    p = fmaf(p, f, 2.402265069e-1f);
    p = fmaf(p, f, 6.931471806e-1f);
    p = fmaf(p, f, 1.0f);
    return p * __int_as_float(e);
}
static __device__ __forceinline__ void cpa(uint32_t dst, const void* src) {
    asm volatile("cp.async.cg.shared.global [%0], [%1], 16;" :: "r"(dst), "l"(src));
}
#define CP_COMMIT() asm volatile("cp.async.commit_group;" ::: "memory")
#define CP_WAIT1()  asm volatile("cp.async.wait_group 1;" ::: "memory")

// ---------------- kernel 1: fp32 -> fp16 conversion ----------------
__global__ void k_convert(const float* __restrict__ nodes,
                          const float* __restrict__ Wn,
                          const float* __restrict__ Wv) {
    const int nN = SQ * DD / 4, nWn = 2048 * 256 / 4, nWv = 12288 * 256 / 4;
    int stride = gridDim.x * blockDim.x;
    for (int idx = blockIdx.x * blockDim.x + threadIdx.x; idx < nN + nWn + nWv; idx += stride) {
        const float* src; __half* dst; int j;
        if (idx < nN)            { src = nodes; dst = g_nodes; j = idx; }
        else if (idx < nN + nWn) { src = Wn;    dst = g_Wn;    j = idx - nN; }
        else                     { src = Wv;    dst = g_Wv;    j = idx - nN - nWn; }
        float4 v = ((const float4*)src)[j];
        ((__half2*)dst)[2 * j]     = __floats2half2_rn(v.x, v.y);
        ((__half2*)dst)[2 * j + 1] = __floats2half2_rn(v.z, v.w);
    }
}

// ---------------- kernel 2: pos/rot projections (K=6 / K=4) ----------------
__global__ void k_posrot(const float* __restrict__ pos, const float* __restrict__ rot,
                         const float* __restrict__ Wp, const float* __restrict__ bp,
                         const float* __restrict__ Wr) {
    int idx = blockIdx.x * blockDim.x + threadIdx.x;
    if (idx >= SQ * 2048) return;
    int s = idx >> 11, r = idx & 2047;
    float ap = bp[r];
#pragma unroll
    for (int i = 0; i < 6; i++) ap = fmaf(pos[s * 6 + i], Wp[r * 6 + i], ap);
    float ar = 0.f;
#pragma unroll
    for (int i = 0; i < 4; i++) ar = fmaf(rot[s * 4 + i], Wr[r * 4 + i], ar);
    int h = r >> 7, cc = r & 127;
    if (cc < 64) {
        g_K[(16 + h) * SQ * CCH + s * CCH + cc] = __float2half_rn(ap);
        g_K[(32 + h) * SQ * CCH + s * CCH + cc] = __float2half_rn(ar);
    } else {
        g_Qm[(16 + h) * SQ * CCH + s * CCH + cc - 64] = __float2half_rn(ap);
        g_Qm[(32 + h) * SQ * CCH + s * CCH + cc - 64] = __float2half_rn(ar);
    }
}

// ---------------- kernel 3: fp16 mma GEMM: nodes @ W^T + bias, scatter ----------------
template <int MODE>
__global__ __launch_bounds__(256) void k_gemm(const float* __restrict__ bias) {
    __shared__ __half As[128 * 64];
    __shared__ __half Bs[128 * 64];
    const __half* Wg = (MODE == 0) ? g_Wn : g_Wv;
    int mb = blockIdx.x * 128, nb = blockIdx.y * 128;
    int t = threadIdx.x, lane = t & 31, w = t >> 5;
    int wm = w & 3, wn = w >> 2;
    float c[2][8][4];
#pragma unroll
    for (int a = 0; a < 2; a++)
#pragma unroll
        for (int b = 0; b < 8; b++)
#pragma unroll
            for (int e2 = 0; e2 < 4; e2++) c[a][b][e2] = 0.f;

    for (int kc = 0; kc < 4; kc++) {
#pragma unroll
        for (int i = 0; i < 4; i++) {
            int l = t + i * 256;
            int row = l >> 3, ch = l & 7;
            int sw = (ch ^ (row & 7)) * 8;
            *(int4*)&As[row * 64 + sw] = *(const int4*)&g_nodes[(mb + row) * 256 + kc * 64 + ch * 8];
            *(int4*)&Bs[row * 64 + sw] = *(const int4*)&Wg[(nb + row) * 256 + kc * 64 + ch * 8];
        }
        __syncthreads();
#pragma unroll
        for (int ks = 0; ks < 4; ks++) {
            uint32_t a[2][4];
#pragma unroll
            for (int ms = 0; ms < 2; ms++) {
                int row = wm * 32 + ms * 16 + (lane & 15);
                int col = (ks * 16 + ((lane >> 4) << 3)) ^ ((row & 7) << 3);
                ldsm4(a[ms], sm_u32(&As[row * 64 + col]));
            }
#pragma unroll
            for (int p = 0; p < 4; p++) {
                uint32_t b[4];
                int row = wn * 64 + p * 16 + (lane & 7) + ((lane & 16) >> 1);
                int col = (ks * 16 + (lane & 8)) ^ ((row & 7) << 3);
                ldsm4(b, sm_u32(&Bs[row * 64 + col]));
                mma16816(c[0][2 * p],     a[0], b);
                mma16816(c[0][2 * p + 1], a[0], b + 2);
                mma16816(c[1][2 * p],     a[1], b);
                mma16816(c[1][2 * p + 1], a[1], b + 2);
            }
        }
        __syncthreads();
    }
#pragma unroll
    for (int ms = 0; ms < 2; ms++) {
        int r0 = mb + wm * 32 + ms * 16 + (lane >> 2);
#pragma unroll
        for (int nt = 0; nt < 8; nt++) {
            int n = nb + wn * 64 + nt * 8 + 2 * (lane & 3);
            float b0 = bias[n], b1 = bias[n + 1];
            uint32_t lo = packh2(c[ms][nt][0] + b0, c[ms][nt][1] + b1);
            uint32_t hi = packh2(c[ms][nt][2] + b0, c[ms][nt][3] + b1);
            if (MODE == 0) {
                int h = n >> 7, ccv = n & 127;
                __half* dst = (ccv < 64) ? (g_K + h * SQ * CCH + ccv)
                                         : (g_Qm + h * SQ * CCH + (ccv - 64));
                *(uint32_t*)&dst[r0 * CCH]       = lo;
                *(uint32_t*)&dst[(r0 + 8) * CCH] = hi;
            } else {
                int h = n >> 8, d = n & 255;
                __half* dst = g_V + h * SQ * DD + d;
                *(uint32_t*)&dst[r0 * DD]       = lo;
                *(uint32_t*)&dst[(r0 + 8) * DD] = hi;
            }
        }
    }
}

// ---------------- kernel 4: fused attention (mma.sync + cp.async 2-stage) ----------------
// grid (16 i-tiles of 128, 48 heads). 8 warps x 16 rows x 256 cols per CTA.
// Logits bounded (~+-1.5) -> plain sum-exp softmax, no max subtraction.
#define STGSZ 40960                      // Q 8KB + V 32KB per stage
#define QOFF(s) ((s) * STGSZ)
#define VOFF(s) ((s) * STGSZ + 8192)
#define ATTN_SMEM (2 * STGSZ)            // 81920 B

static __device__ __forceinline__ void prefetch_stage(uint32_t sb, int s,
                                                      const __half* qg, const __half* vg,
                                                      int jt, int t) {
#pragma unroll
    for (int i = 0; i < 2; i++) {          // Q tile 64 x 64 halves
        int idx = t + i * 256;
        int row = idx >> 3, ch = idx & 7;
        uint32_t off = (uint32_t)((row * 64 + ((ch ^ (row & 7)) * 8)) * 2);
        cpa(sb + QOFF(s) + off, qg + (jt * 64 + row) * CCH + ch * 8);
    }
#pragma unroll
    for (int i = 0; i < 8; i++) {          // V tile 64 x 256 halves
        int idx = t + i * 256;
        int row = idx >> 5, ch = idx & 31;
        uint32_t off = (uint32_t)((row * 256 + ((ch ^ (row & 7)) * 8)) * 2);
        cpa(sb + VOFF(s) + off, vg + (jt * 64 + row) * DD + ch * 8);
    }
}

__global__ __launch_bounds__(256, 1) void k_attn() {
    extern __shared__ char smem[];
    uint32_t sb = sm_u32(smem);
    int t = threadIdx.x, lane = t & 31, w = t >> 5;
    int ib = blockIdx.x * 128;
    int h = blockIdx.y;
    bool isrot = (h >= 32);

    const __half* qg = g_Qm + h * SQ * CCH;
    const __half* vg = g_V + h * SQ * DD;

    // K a-frags from global (16 rows per warp, register-resident whole kernel)
    uint32_t ak[4][4];
    {
        const __half* kb = g_K + h * SQ * CCH + (ib + w * 16) * CCH;
        int r = lane >> 2, c0 = 2 * (lane & 3);
#pragma unroll
        for (int ks = 0; ks < 4; ks++) {
            int cb = ks * 16 + c0;
            ak[ks][0] = *(const uint32_t*)&kb[r * CCH + cb];
            ak[ks][1] = *(const uint32_t*)&kb[(r + 8) * CCH + cb];
            ak[ks][2] = *(const uint32_t*)&kb[r * CCH + cb + 8];
            ak[ks][3] = *(const uint32_t*)&kb[(r + 8) * CCH + cb + 8];
        }
    }

    float o[32][4];
#pragma unroll
    for (int i = 0; i < 32; i++) { o[i][0] = 0.f; o[i][1] = 0.f; o[i][2] = 0.f; o[i][3] = 0.f; }
    float l0 = 0.f, l1 = 0.f;

    prefetch_stage(sb, 0, qg, vg, 0, t);
    CP_COMMIT();

    for (int jt = 0; jt < 32; jt++) {
        __syncthreads();                       // all warps done reading buf[(jt+1)&1] (iter jt-1)
        if (jt + 1 < 32) prefetch_stage(sb, (jt + 1) & 1, qg, vg, jt + 1, t);
        CP_COMMIT();
        CP_WAIT1();                            // group jt complete (newest group stays pending)
        __syncthreads();                       // make stage jt visible to all warps

        uint32_t qbase = sb + QOFF(jt & 1);
        uint32_t vbase = sb + VOFF(jt & 1);

        float sc[8][4];
#pragma unroll
        for (int i = 0; i < 8; i++) { sc[i][0] = 0.f; sc[i][1] = 0.f; sc[i][2] = 0.f; sc[i][3] = 0.f; }
        // S = K_i @ Q_j^T  (16 x 64 per warp)
#pragma unroll
        for (int ks = 0; ks < 4; ks++) {
#pragma unroll
            for (int p = 0; p < 4; p++) {
                uint32_t qb[4];
                int row = p * 16 + (lane & 7) + ((lane & 16) >> 1);
                int col = (ks * 16 + (lane & 8)) ^ ((row & 7) << 3);
                ldsm4(qb, qbase + (row * 64 + col) * 2);
                mma16816(sc[2 * p],     ak[ks], qb);
                mma16816(sc[2 * p + 1], ak[ks], qb + 2);
            }
        }
        // square (rot heads), scale 1/sqrt(16), exp, sum
#pragma unroll
        for (int i = 0; i < 8; i++) {
#pragma unroll
            for (int q2 = 0; q2 < 4; q2++) {
                float x = sc[i][q2];
                if (isrot) x = x * x;
                sc[i][q2] = fexp(x * 0.25f);
            }
            l0 += sc[i][0] + sc[i][1];
            l1 += sc[i][2] + sc[i][3];
        }
        // O += P @ V  (P cfrag -> A-frag identity, V via ldmatrix.trans)
#pragma unroll
        for (int ks = 0; ks < 4; ks++) {
            uint32_t pa[4];
            pa[0] = packh2(sc[2 * ks][0],     sc[2 * ks][1]);
            pa[1] = packh2(sc[2 * ks][2],     sc[2 * ks][3]);
            pa[2] = packh2(sc[2 * ks + 1][0], sc[2 * ks + 1][1]);
            pa[3] = packh2(sc[2 * ks + 1][2], sc[2 * ks + 1][3]);
#pragma unroll
            for (int ndp = 0; ndp < 16; ndp++) {
                uint32_t vb[4];
                int row = ks * 16 + (lane & 15);
                int col = (ndp * 16 + ((lane >> 4) << 3)) ^ ((row & 7) << 3);
                ldsm4t(vb, vbase + (row * 256 + col) * 2);
                mma16816(o[2 * ndp],     pa, vb);
                mma16816(o[2 * ndp + 1], pa, vb + 2);
            }
        }
    }
    // softmax denominators (quad reduce), scale, write per-head partial bucket
    l0 += __shfl_xor_sync(0xffffffffu, l0, 1);
    l0 += __shfl_xor_sync(0xffffffffu, l0, 2);
    l1 += __shfl_xor_sync(0xffffffffu, l1, 1);
    l1 += __shfl_xor_sync(0xffffffffu, l1, 2);
    float inv0 = 1.f / l0, inv1 = 1.f / l1;
    int r0 = ib + w * 16 + (lane >> 2);
    int cbase = 2 * (lane & 3);
    float* dst = g_part[h];
#pragma unroll
    for (int nt = 0; nt < 32; nt++) {
        int col = nt * 8 + cbase;
        float2 v0 = make_float2(o[nt][0] * inv0, o[nt][1] * inv0);
        float2 v1 = make_float2(o[nt][2] * inv1, o[nt][3] * inv1);
        *(float2*)&dst[r0 * DD + col]       = v0;
        *(float2*)&dst[(r0 + 8) * DD + col] = v1;
    }
}

// ---------------- kernel 5: deterministic 48-way reduction ----------------
__global__ void k_reduce(float* __restrict__ out) {
    int i = blockIdx.x * blockDim.x + threadIdx.x;   // float4 index
    float4 acc = make_float4(0.f, 0.f, 0.f, 0.f);
#pragma unroll
    for (int b = 0; b < NGRP; b++) {
        float4 v = *(const float4*)&g_part[b][i * 4];
        acc.x += v.x; acc.y += v.y; acc.z += v.z; acc.w += v.w;
    }
    ((float4*)out)[i] = acc;
}

// ---------------- launch ----------------
extern "C" void kernel_launch(void* const* d_in, const int* in_sizes, int n_in,
                              void* d_out, int out_size) {
    const float* nodes = (const float*)d_in[0];
    const float* pos   = (const float*)d_in[1];
    const float* rot   = (const float*)d_in[2];
    const float* Wn    = (const float*)d_in[3];
    const float* bn    = (const float*)d_in[4];
    const float* Wp    = (const float*)d_in[5];
    const float* bp    = (const float*)d_in[6];
    const float* Wr    = (const float*)d_in[7];
    const float* Wv    = (const float*)d_in[8];
    const float* bv    = (const float*)d_in[9];
    (void)in_sizes; (void)n_in; (void)out_size;

    cudaFuncSetAttribute(k_attn, cudaFuncAttributeMaxDynamicSharedMemorySize, ATTN_SMEM);

    k_convert<<<4096, 256>>>(nodes, Wn, Wv);
    k_posrot<<<(SQ * 2048) / 256, 256>>>(pos, rot, Wp, bp, Wr);
    k_gemm<0><<<dim3(16, 16), 256>>>(bn);
    k_gemm<1><<<dim3(16, 96), 256>>>(bv);
    k_attn<<<dim3(16, TH), 256, ATTN_SMEM>>>();
    k_reduce<<<512, 256>>>((float*)d_out);
}